// round 1
// baseline (speedup 1.0000x reference)
#include <cuda_runtime.h>
#include <cstdint>
#include <cstddef>

#define N_NODES 50000
#define N_EDGES 800000
#define HID 512

typedef unsigned long long ull;

// Scratch (device globals: no allocation allowed in kernel_launch)
__device__ __align__(16) float g_U[(size_t)N_NODES * HID];   // pe @ W[128:192]
__device__ __align__(16) float g_V[(size_t)N_NODES * HID];   // pe @ W[192:256]
__device__ __align__(16) float g_c0[HID];                    // node const: type0@W3 + b
__device__ __align__(16) float g_c1[HID];                    // edge const: ef@W0 + type1@W3 + b
__device__ int g_idx64;

__device__ __forceinline__ ull pack2(float x, float y) {
    ull r; asm("mov.b64 %0, {%1,%2};" : "=l"(r) : "f"(x), "f"(y)); return r;
}
__device__ __forceinline__ void unpack2(ull p, float& x, float& y) {
    asm("mov.b64 {%0,%1}, %2;" : "=f"(x), "=f"(y) : "l"(p));
}
#define FFMA2(d, a, b, c) \
    asm("fma.rn.f32x2 %0, %1, %2, %3;" : "=l"(d) : "l"(a), "l"(b), "l"(c))

// ---------------------------------------------------------------------------
// Detect whether edge_index arrived as int64 (JAX x64 on) or int32.
// Values < 50000, so int64 high words are always 0. Check odd words of the
// first 64 ints: all zero => int64.
// ---------------------------------------------------------------------------
__global__ void detect_kernel(const int* __restrict__ ei) {
    if (threadIdx.x == 0 && blockIdx.x == 0) {
        int is64 = 1;
        #pragma unroll
        for (int i = 1; i < 64; i += 2)
            if (ei[i] != 0) is64 = 0;
        g_idx64 = is64;
    }
}

// ---------------------------------------------------------------------------
// Constant 512-vectors for node rows and edge rows.
// c0[j] = b[j] + sum_k tte[0][k] * W[256+k][j]
// c1[j] = b[j] + sum_k (tte[1][k] * W[256+k][j] + ef[k] * W[k][j])
// ---------------------------------------------------------------------------
__global__ void const_kernel(const float* __restrict__ ef,
                             const float* __restrict__ tte,
                             const float* __restrict__ W,
                             const float* __restrict__ b) {
    int j = blockIdx.x * blockDim.x + threadIdx.x;
    if (j >= HID) return;
    float s0 = b[j], s1 = b[j];
    #pragma unroll 4
    for (int k = 0; k < 128; k++) {
        float w3 = W[(size_t)(256 + k) * HID + j];
        s0 += tte[k] * w3;
        s1 += tte[128 + k] * w3 + ef[k] * W[(size_t)k * HID + j];
    }
    g_c0[j] = s0;
    g_c1[j] = s1;
}

// ---------------------------------------------------------------------------
// GEMM U/V: [50000 x 64] @ [64 x 512] twice (W1 and W2), f32x2 packed FMA.
// Tile: BM=64, BN=128, K=64 (single stage). 256 threads, each 4x8 outputs.
// grid.y in 0..7: y<4 -> U cols y*128 (W rows 128..191)
//                 y>=4 -> V cols (y-4)*128 (W rows 192..255)
// ---------------------------------------------------------------------------
__global__ void __launch_bounds__(256)
gemm_uv_kernel(const float* __restrict__ pe, const float* __restrict__ W) {
    __shared__ float As[64 * 68];    // [m][k], row pad 68
    __shared__ float Bs[64 * 132];   // [k][n], row pad 132

    const int tid = threadIdx.x;
    const int tx = tid & 15, ty = tid >> 4;
    const int row0 = blockIdx.x * 64;
    const int ny = blockIdx.y;
    const int krow = (ny < 4) ? 128 : 192;
    const int ncol0 = (ny & 3) * 128;
    const float* Wbase = W + (size_t)krow * HID + ncol0;
    float* Out = (ny < 4) ? g_U : g_V;

    // Load A tile (64 x 64) as float4, coalesced
    const float4* pe4 = (const float4*)pe;
    #pragma unroll
    for (int i = 0; i < 4; i++) {
        int idx = tid + i * 256;            // 0..1023
        int m = idx >> 4, k4 = idx & 15;
        int r = row0 + m;
        float4 v = (r < N_NODES) ? __ldg(&pe4[(size_t)r * 16 + k4])
                                 : make_float4(0.f, 0.f, 0.f, 0.f);
        *(float4*)&As[m * 68 + k4 * 4] = v;
    }
    // Load B tile (64 x 128)
    #pragma unroll
    for (int i = 0; i < 8; i++) {
        int idx = tid + i * 256;            // 0..2047
        int k = idx >> 5, n4 = idx & 31;
        float4 v = __ldg((const float4*)(Wbase + (size_t)k * HID) + n4);
        *(float4*)&Bs[k * 132 + n4 * 4] = v;
    }
    __syncthreads();

    ull acc[16];
    #pragma unroll
    for (int i = 0; i < 16; i++) acc[i] = 0ull;

    #pragma unroll 8
    for (int k = 0; k < 64; k++) {
        const ull* brow = (const ull*)&Bs[k * 132 + tx * 8];
        ull b0 = brow[0], b1 = brow[1], b2 = brow[2], b3 = brow[3];
        #pragma unroll
        for (int m = 0; m < 4; m++) {
            float av = As[(ty * 4 + m) * 68 + k];
            ull aa = pack2(av, av);
            FFMA2(acc[m * 4 + 0], aa, b0, acc[m * 4 + 0]);
            FFMA2(acc[m * 4 + 1], aa, b1, acc[m * 4 + 1]);
            FFMA2(acc[m * 4 + 2], aa, b2, acc[m * 4 + 2]);
            FFMA2(acc[m * 4 + 3], aa, b3, acc[m * 4 + 3]);
        }
    }

    #pragma unroll
    for (int m = 0; m < 4; m++) {
        int r = row0 + ty * 4 + m;
        if (r < N_NODES) {
            float4 o0, o1;
            unpack2(acc[m * 4 + 0], o0.x, o0.y);
            unpack2(acc[m * 4 + 1], o0.z, o0.w);
            unpack2(acc[m * 4 + 2], o1.x, o1.y);
            unpack2(acc[m * 4 + 3], o1.z, o1.w);
            float* dst = Out + (size_t)r * HID + ncol0 + tx * 8;
            *(float4*)dst = o0;
            *(float4*)(dst + 4) = o1;
        }
    }
}

// ---------------------------------------------------------------------------
// Node rows: out[i] = nf[i] @ W[0:128] + U[i] + V[i] + c0
// Tile: BM=64, BN=128, K=128 in two 64-stages. grid.y in 0..3 (col block).
// ---------------------------------------------------------------------------
__global__ void __launch_bounds__(256)
gemm_nodes_kernel(const float* __restrict__ nf, const float* __restrict__ W,
                  float* __restrict__ out) {
    __shared__ float As[64 * 68];
    __shared__ float Bs[64 * 132];

    const int tid = threadIdx.x;
    const int tx = tid & 15, ty = tid >> 4;
    const int row0 = blockIdx.x * 64;
    const int col0 = blockIdx.y * 128;

    ull acc[16];
    #pragma unroll
    for (int i = 0; i < 16; i++) acc[i] = 0ull;

    for (int s = 0; s < 2; s++) {
        #pragma unroll
        for (int i = 0; i < 4; i++) {
            int idx = tid + i * 256;
            int m = idx >> 4, k4 = idx & 15;
            int r = row0 + m;
            float4 v = (r < N_NODES)
                ? __ldg((const float4*)(nf + (size_t)r * 128 + s * 64) + k4)
                : make_float4(0.f, 0.f, 0.f, 0.f);
            *(float4*)&As[m * 68 + k4 * 4] = v;
        }
        #pragma unroll
        for (int i = 0; i < 8; i++) {
            int idx = tid + i * 256;
            int k = idx >> 5, n4 = idx & 31;
            float4 v = __ldg((const float4*)(W + (size_t)(s * 64 + k) * HID + col0) + n4);
            *(float4*)&Bs[k * 132 + n4 * 4] = v;
        }
        __syncthreads();

        #pragma unroll 8
        for (int k = 0; k < 64; k++) {
            const ull* brow = (const ull*)&Bs[k * 132 + tx * 8];
            ull b0 = brow[0], b1 = brow[1], b2 = brow[2], b3 = brow[3];
            #pragma unroll
            for (int m = 0; m < 4; m++) {
                float av = As[(ty * 4 + m) * 68 + k];
                ull aa = pack2(av, av);
                FFMA2(acc[m * 4 + 0], aa, b0, acc[m * 4 + 0]);
                FFMA2(acc[m * 4 + 1], aa, b1, acc[m * 4 + 1]);
                FFMA2(acc[m * 4 + 2], aa, b2, acc[m * 4 + 2]);
                FFMA2(acc[m * 4 + 3], aa, b3, acc[m * 4 + 3]);
            }
        }
        __syncthreads();
    }

    const float4* c0p = (const float4*)(g_c0 + col0 + tx * 8);
    float4 ca = c0p[0], cb = c0p[1];

    #pragma unroll
    for (int m = 0; m < 4; m++) {
        int r = row0 + ty * 4 + m;
        if (r < N_NODES) {
            const float4* up = (const float4*)(g_U + (size_t)r * HID + col0 + tx * 8);
            const float4* vp = (const float4*)(g_V + (size_t)r * HID + col0 + tx * 8);
            float4 u0 = up[0], u1 = up[1];
            float4 v0 = vp[0], v1 = vp[1];
            float4 o0, o1;
            unpack2(acc[m * 4 + 0], o0.x, o0.y);
            unpack2(acc[m * 4 + 1], o0.z, o0.w);
            unpack2(acc[m * 4 + 2], o1.x, o1.y);
            unpack2(acc[m * 4 + 3], o1.z, o1.w);
            o0.x += u0.x + v0.x + ca.x;  o0.y += u0.y + v0.y + ca.y;
            o0.z += u0.z + v0.z + ca.z;  o0.w += u0.w + v0.w + ca.w;
            o1.x += u1.x + v1.x + cb.x;  o1.y += u1.y + v1.y + cb.y;
            o1.z += u1.z + v1.z + cb.z;  o1.w += u1.w + v1.w + cb.w;
            float* dst = out + (size_t)r * HID + col0 + tx * 8;
            __stcs((float4*)dst, o0);
            __stcs((float4*)(dst + 4), o1);
        }
    }
}

// ---------------------------------------------------------------------------
// Edge rows: out[N+e] = U[src(e)] + V[dst(e)] + c1.  Memory-bound gather-add.
// One thread per float4 of output; 128 consecutive threads share one edge.
// Output stored with .cs (streaming) to preserve L2 for U/V gathers.
// ---------------------------------------------------------------------------
__global__ void __launch_bounds__(256)
edge_kernel(const int* __restrict__ ei, float* __restrict__ out) {
    long long t = (long long)blockIdx.x * 256 + threadIdx.x;
    int e = (int)(t >> 7);
    int c = (int)(t & 127);
    if (e >= N_EDGES) return;

    int src, dst;
    if (g_idx64) {
        src = ei[2 * (size_t)e];
        dst = ei[2 * ((size_t)N_EDGES + e)];
    } else {
        src = ei[e];
        dst = ei[N_EDGES + e];
    }

    float4 u = __ldg((const float4*)(g_U + (size_t)src * HID) + c);
    float4 v = __ldg((const float4*)(g_V + (size_t)dst * HID) + c);
    float4 cc = __ldg((const float4*)g_c1 + c);
    float4 o = make_float4(u.x + v.x + cc.x, u.y + v.y + cc.y,
                           u.z + v.z + cc.z, u.w + v.w + cc.w);
    __stcs((float4*)(out + (size_t)(N_NODES + e) * HID) + c, o);
}

// ---------------------------------------------------------------------------
extern "C" void kernel_launch(void* const* d_in, const int* in_sizes, int n_in,
                              void* d_out, int out_size) {
    // Defensive remap by element count (all 7 are distinct).
    const void* ptr[7] = {d_in[0], d_in[1], d_in[2], d_in[3], d_in[4], d_in[5], d_in[6]};
    const int want[7] = {6553600, 3200000, 128, 256, 196608, 512, 1600000};
    const void* mapped[7];
    for (int w = 0; w < 7; w++) {
        mapped[w] = ptr[w < n_in ? w : 0];  // positional fallback
        for (int i = 0; i < n_in && i < 7; i++)
            if (in_sizes[i] == want[w]) { mapped[w] = ptr[i]; break; }
    }
    const float* nf  = (const float*)mapped[0];
    const float* pe  = (const float*)mapped[1];
    const float* ef  = (const float*)mapped[2];
    const float* tte = (const float*)mapped[3];
    const float* W   = (const float*)mapped[4];
    const float* b   = (const float*)mapped[5];
    const int*   ei  = (const int*)mapped[6];
    float* out = (float*)d_out;

    detect_kernel<<<1, 32>>>(ei);
    const_kernel<<<2, 256>>>(ef, tte, W, b);
    gemm_uv_kernel<<<dim3((N_NODES + 63) / 64, 8), 256>>>(pe, W);
    gemm_nodes_kernel<<<dim3((N_NODES + 63) / 64, 4), 256>>>(nf, W, out);
    edge_kernel<<<(N_EDGES * 128) / 256, 256>>>(ei, out);
}

// round 2
// speedup vs baseline: 1.4756x; 1.4756x over previous
#include <cuda_runtime.h>
#include <cuda_fp16.h>
#include <cstdint>
#include <cstddef>

#define N_NODES 50000
#define N_EDGES 800000
#define HID 512
#define NB_ROW 391   // ceil(50000/128)

typedef unsigned long long ull;

// Scratch (device globals; no allocation allowed)
__device__ __align__(16) __half g_Uh[(size_t)N_NODES * HID];  // pe @ W[128:192], fp16
__device__ __align__(16) __half g_Vh[(size_t)N_NODES * HID];  // pe @ W[192:256], fp16
__device__ __align__(16) float  g_Wc[64 * HID];               // W1 + W2 (rows 128..191 + 192..255)
__device__ __align__(16) float  g_c0[HID];                    // node const: type0@W3 + b
__device__ __align__(16) float  g_c1[HID];                    // edge const: ef@W0 + type1@W3 + b
__device__ int g_idx64;

__device__ __forceinline__ ull dup2(float x) {
    ull r; asm("mov.b64 %0, {%1,%1};" : "=l"(r) : "f"(x)); return r;
}
__device__ __forceinline__ void unpack2(ull p, float& x, float& y) {
    asm("mov.b64 {%0,%1}, %2;" : "=f"(x), "=f"(y) : "l"(p));
}
#define FFMA2(d, a, b, c) \
    asm("fma.rn.f32x2 %0, %1, %2, %3;" : "=l"(d) : "l"(a), "l"(b), "l"(c))

// ---------------------------------------------------------------------------
// int64-vs-int32 edge_index detection: indices < 50000, so int64 high words
// are all zero. Check odd 32-bit words of the first 64.
// ---------------------------------------------------------------------------
__global__ void detect_kernel(const int* __restrict__ ei) {
    if (threadIdx.x == 0) {
        int is64 = 1;
        #pragma unroll
        for (int i = 1; i < 64; i += 2)
            if (ei[i] != 0) is64 = 0;
        g_idx64 = is64;
    }
}

// c0[j] = b[j] + sum_k tte[0][k]*W[256+k][j]
// c1[j] = b[j] + sum_k (tte[1][k]*W[256+k][j] + ef[k]*W[k][j])
__global__ void prep_const_kernel(const float* __restrict__ ef,
                                  const float* __restrict__ tte,
                                  const float* __restrict__ W,
                                  const float* __restrict__ b) {
    int j = blockIdx.x * blockDim.x + threadIdx.x;
    if (j >= HID) return;
    float s0 = b[j], s1 = b[j];
    #pragma unroll 4
    for (int k = 0; k < 128; k++) {
        float w3 = W[(size_t)(256 + k) * HID + j];
        s0 += tte[k] * w3;
        s1 += tte[128 + k] * w3 + ef[k] * W[(size_t)k * HID + j];
    }
    g_c0[j] = s0;
    g_c1[j] = s1;
}

// g_Wc = W[128:192] + W[192:256]   (64 x 512)
__global__ void prep_wc_kernel(const float* __restrict__ W) {
    int i = blockIdx.x * blockDim.x + threadIdx.x;   // float4 index, 8192 total
    float4 a = __ldg((const float4*)(W + 128 * HID) + i);
    float4 c = __ldg((const float4*)(W + 192 * HID) + i);
    a.x += c.x; a.y += c.y; a.z += c.z; a.w += c.w;
    ((float4*)g_Wc)[i] = a;
}

// ---------------------------------------------------------------------------
// Fused GEMM. 128x128 block tile, BK=32, 256 threads, 8x8 per thread, f32x2.
// A stored transposed in smem As[k][m] with XOR swizzle so inner-loop A reads
// are broadcast LDS.128. Jobs:
//   blockIdx < NB_ROW*8 :  U/V  (pe[50000x64] @ W1 / W2 -> fp16 scratch)
//   else                :  node (nf|pe [50000x192] @ [W0;Wc] + c0 -> out)
// ---------------------------------------------------------------------------
__global__ void __launch_bounds__(256, 2)
gemm_kernel(const float* __restrict__ nf, const float* __restrict__ pe,
            const float* __restrict__ W, float* __restrict__ out) {
    __shared__ float As[32 * 132];   // [k][m], pad 132
    __shared__ float Bs[32 * 132];   // [k][n], pad 132

    const int tid = threadIdx.x;
    const int tx8 = (tid & 15) * 8;          // n offset
    const int ty8 = (tid >> 4) * 8;          // m offset
    const int bi = blockIdx.x;

    int row0, col0, nstages, is_node, uv = 0;
    if (bi < NB_ROW * 8) {
        is_node = 0;
        row0 = (bi >> 3) * 128;
        uv   = (bi & 7) >> 2;
        col0 = (bi & 3) * 128;
        nstages = 2;                         // K = 64
    } else {
        is_node = 1;
        int jb = bi - NB_ROW * 8;
        row0 = (jb >> 2) * 128;
        col0 = (jb & 3) * 128;
        nstages = 6;                         // K = 192
    }

    ull acc[32];
    #pragma unroll
    for (int i = 0; i < 32; i++) acc[i] = 0ull;

    for (int s = 0; s < nstages; s++) {
        // Resolve A source (row-major, length L) and B source for this stage
        const float* Asrc; int L, kcol0;
        const float* Bsrc;
        if (!is_node) {
            Asrc = pe; L = 64; kcol0 = s * 32;
            Bsrc = W + (size_t)(128 + 64 * uv + s * 32) * HID + col0;
        } else {
            int kg = s * 32;
            if (kg < 128) { Asrc = nf; L = 128; kcol0 = kg;
                            Bsrc = W + (size_t)kg * HID + col0; }
            else          { Asrc = pe; L = 64;  kcol0 = kg - 128;
                            Bsrc = g_Wc + (size_t)(kg - 128) * HID + col0; }
        }

        // Load A tile (128 rows x 32 k) -> As[k][m^swz], 4 float4 per thread
        #pragma unroll
        for (int i = 0; i < 4; i++) {
            int idx = i * 256 + tid;         // 0..1023
            int m = idx >> 3, kq = idx & 7;  // kq: float4 index along k
            int r = row0 + m;
            float4 v = (r < N_NODES)
                ? __ldg((const float4*)(Asrc + (size_t)r * L + kcol0) + kq)
                : make_float4(0.f, 0.f, 0.f, 0.f);
            int ms = m ^ (kq << 2);
            As[(kq * 4 + 0) * 132 + ms] = v.x;
            As[(kq * 4 + 1) * 132 + ms] = v.y;
            As[(kq * 4 + 2) * 132 + ms] = v.z;
            As[(kq * 4 + 3) * 132 + ms] = v.w;
        }
        // Load B tile (32 k x 128 n), 4 float4 per thread
        #pragma unroll
        for (int i = 0; i < 4; i++) {
            int idx = i * 256 + tid;         // 0..1023
            int k = idx >> 5, n4 = idx & 31;
            float4 v = __ldg((const float4*)(Bsrc + (size_t)k * HID) + n4);
            *(float4*)&Bs[k * 132 + n4 * 4] = v;
        }
        __syncthreads();

        #pragma unroll 8
        for (int k = 0; k < 32; k++) {
            const int x = (k >> 2) << 2;
            const float4 a0 = *(const float4*)&As[k * 132 + (ty8 ^ x)];
            const float4 a1 = *(const float4*)&As[k * 132 + ((ty8 + 4) ^ x)];
            const ulonglong2* bp = (const ulonglong2*)&Bs[k * 132 + tx8];
            const ulonglong2 B0 = bp[0], B1 = bp[1];
            ull aa;
            aa = dup2(a0.x);
            FFMA2(acc[ 0], aa, B0.x, acc[ 0]); FFMA2(acc[ 1], aa, B0.y, acc[ 1]);
            FFMA2(acc[ 2], aa, B1.x, acc[ 2]); FFMA2(acc[ 3], aa, B1.y, acc[ 3]);
            aa = dup2(a0.y);
            FFMA2(acc[ 4], aa, B0.x, acc[ 4]); FFMA2(acc[ 5], aa, B0.y, acc[ 5]);
            FFMA2(acc[ 6], aa, B1.x, acc[ 6]); FFMA2(acc[ 7], aa, B1.y, acc[ 7]);
            aa = dup2(a0.z);
            FFMA2(acc[ 8], aa, B0.x, acc[ 8]); FFMA2(acc[ 9], aa, B0.y, acc[ 9]);
            FFMA2(acc[10], aa, B1.x, acc[10]); FFMA2(acc[11], aa, B1.y, acc[11]);
            aa = dup2(a0.w);
            FFMA2(acc[12], aa, B0.x, acc[12]); FFMA2(acc[13], aa, B0.y, acc[13]);
            FFMA2(acc[14], aa, B1.x, acc[14]); FFMA2(acc[15], aa, B1.y, acc[15]);
            aa = dup2(a1.x);
            FFMA2(acc[16], aa, B0.x, acc[16]); FFMA2(acc[17], aa, B0.y, acc[17]);
            FFMA2(acc[18], aa, B1.x, acc[18]); FFMA2(acc[19], aa, B1.y, acc[19]);
            aa = dup2(a1.y);
            FFMA2(acc[20], aa, B0.x, acc[20]); FFMA2(acc[21], aa, B0.y, acc[21]);
            FFMA2(acc[22], aa, B1.x, acc[22]); FFMA2(acc[23], aa, B1.y, acc[23]);
            aa = dup2(a1.z);
            FFMA2(acc[24], aa, B0.x, acc[24]); FFMA2(acc[25], aa, B0.y, acc[25]);
            FFMA2(acc[26], aa, B1.x, acc[26]); FFMA2(acc[27], aa, B1.y, acc[27]);
            aa = dup2(a1.w);
            FFMA2(acc[28], aa, B0.x, acc[28]); FFMA2(acc[29], aa, B0.y, acc[29]);
            FFMA2(acc[30], aa, B1.x, acc[30]); FFMA2(acc[31], aa, B1.y, acc[31]);
        }
        __syncthreads();
    }

    if (!is_node) {
        __half* Out = uv ? g_Vh : g_Uh;
        #pragma unroll
        for (int m = 0; m < 8; m++) {
            int r = row0 + ty8 + m;
            if (r < N_NODES) {
                float f0, f1, f2, f3, f4, f5, f6, f7;
                unpack2(acc[m * 4 + 0], f0, f1);
                unpack2(acc[m * 4 + 1], f2, f3);
                unpack2(acc[m * 4 + 2], f4, f5);
                unpack2(acc[m * 4 + 3], f6, f7);
                uint4 pk;
                __half2* ph = (__half2*)&pk;
                ph[0] = __floats2half2_rn(f0, f1);
                ph[1] = __floats2half2_rn(f2, f3);
                ph[2] = __floats2half2_rn(f4, f5);
                ph[3] = __floats2half2_rn(f6, f7);
                *(uint4*)(Out + (size_t)r * HID + col0 + tx8) = pk;
            }
        }
    } else {
        const float4 cA = *(const float4*)&g_c0[col0 + tx8];
        const float4 cB = *(const float4*)&g_c0[col0 + tx8 + 4];
        #pragma unroll
        for (int m = 0; m < 8; m++) {
            int r = row0 + ty8 + m;
            if (r < N_NODES) {
                float4 o0, o1;
                unpack2(acc[m * 4 + 0], o0.x, o0.y);
                unpack2(acc[m * 4 + 1], o0.z, o0.w);
                unpack2(acc[m * 4 + 2], o1.x, o1.y);
                unpack2(acc[m * 4 + 3], o1.z, o1.w);
                o0.x += cA.x; o0.y += cA.y; o0.z += cA.z; o0.w += cA.w;
                o1.x += cB.x; o1.y += cB.y; o1.z += cB.z; o1.w += cB.w;
                float* dst = out + (size_t)r * HID + col0 + tx8;
                __stcs((float4*)dst, o0);
                __stcs((float4*)(dst + 4), o1);
            }
        }
    }
}

// ---------------------------------------------------------------------------
// Edge rows: out[N+e] = Uh[src] + Vh[dst] + c1 (fp16 gather, fp32 out).
// 64 threads per edge, 8 floats (one uint4 of halves) each.
// ---------------------------------------------------------------------------
__global__ void __launch_bounds__(256)
edge_kernel(const int* __restrict__ ei, float* __restrict__ out) {
    long long t = (long long)blockIdx.x * 256 + threadIdx.x;
    int e = (int)(t >> 6);
    int c = (int)(t & 63);
    if (e >= N_EDGES) return;

    int src, dst;
    if (g_idx64) {
        src = ei[2 * (size_t)e];
        dst = ei[2 * ((size_t)N_EDGES + e)];
    } else {
        src = ei[e];
        dst = ei[N_EDGES + e];
    }

    uint4 pu = __ldg((const uint4*)(g_Uh + (size_t)src * HID) + c);
    uint4 pv = __ldg((const uint4*)(g_Vh + (size_t)dst * HID) + c);
    float4 c1a = __ldg((const float4*)g_c1 + c * 2);
    float4 c1b = __ldg((const float4*)g_c1 + c * 2 + 1);

    const __half2* hu = (const __half2*)&pu;
    const __half2* hv = (const __half2*)&pv;
    float2 u0 = __half22float2(hu[0]), u1 = __half22float2(hu[1]);
    float2 u2 = __half22float2(hu[2]), u3 = __half22float2(hu[3]);
    float2 v0 = __half22float2(hv[0]), v1 = __half22float2(hv[1]);
    float2 v2 = __half22float2(hv[2]), v3 = __half22float2(hv[3]);

    float4 o0, o1;
    o0.x = u0.x + v0.x + c1a.x;  o0.y = u0.y + v0.y + c1a.y;
    o0.z = u1.x + v1.x + c1a.z;  o0.w = u1.y + v1.y + c1a.w;
    o1.x = u2.x + v2.x + c1b.x;  o1.y = u2.y + v2.y + c1b.y;
    o1.z = u3.x + v3.x + c1b.z;  o1.w = u3.y + v3.y + c1b.w;

    float* dst_p = out + (size_t)(N_NODES + e) * HID + c * 8;
    __stcs((float4*)dst_p, o0);
    __stcs((float4*)(dst_p + 4), o1);
}

// ---------------------------------------------------------------------------
extern "C" void kernel_launch(void* const* d_in, const int* in_sizes, int n_in,
                              void* d_out, int out_size) {
    // Defensive remap by element count (all 7 distinct).
    const void* ptr[7] = {d_in[0], d_in[1], d_in[2], d_in[3], d_in[4], d_in[5], d_in[6]};
    const int want[7] = {6400000, 3200000, 128, 256, 196608, 512, 1600000};
    const void* mapped[7];
    for (int w = 0; w < 7; w++) {
        mapped[w] = ptr[w < n_in ? w : 0];
        for (int i = 0; i < n_in && i < 7; i++)
            if (in_sizes[i] == want[w]) { mapped[w] = ptr[i]; break; }
    }
    const float* nf  = (const float*)mapped[0];
    const float* pe  = (const float*)mapped[1];
    const float* ef  = (const float*)mapped[2];
    const float* tte = (const float*)mapped[3];
    const float* W   = (const float*)mapped[4];
    const float* b   = (const float*)mapped[5];
    const int*   ei  = (const int*)mapped[6];
    float* out = (float*)d_out;

    detect_kernel<<<1, 32>>>(ei);
    prep_const_kernel<<<2, 256>>>(ef, tte, W, b);
    prep_wc_kernel<<<32, 256>>>(W);                      // 8192 float4
    gemm_kernel<<<NB_ROW * 12, 256>>>(nf, pe, W, out);   // 8 UV + 4 node jobs per row-block
    edge_kernel<<<(N_EDGES * 64) / 256, 256>>>(ei, out);
}

// round 3
// speedup vs baseline: 1.4985x; 1.0155x over previous
#include <cuda_runtime.h>
#include <cuda_fp16.h>
#include <cstdint>
#include <cstddef>

#define N_NODES 50000
#define N_EDGES 800000
#define HID 512
#define NB_ROW 391   // ceil(50000/128)

typedef unsigned long long ull;

// Scratch (device globals; no allocation allowed)
__device__ __align__(16) __half g_Uh[(size_t)N_NODES * HID];  // pe @ W[128:192], fp16
__device__ __align__(16) __half g_Vh[(size_t)N_NODES * HID];  // pe @ W[192:256], fp16
__device__ __align__(16) float  g_Wc[64 * HID];               // W1 + W2
__device__ __align__(16) float  g_c0[HID];                    // node const
__device__ __align__(16) float  g_c1[HID];                    // edge const
__device__ int g_idx64;

__device__ __forceinline__ ull dup2(float x) {
    ull r; asm("mov.b64 %0, {%1,%1};" : "=l"(r) : "f"(x)); return r;
}
__device__ __forceinline__ void unpack2(ull p, float& x, float& y) {
    asm("mov.b64 {%0,%1}, %2;" : "=f"(x), "=f"(y) : "l"(p));
}
#define FFMA2(d, a, b, c) \
    asm("fma.rn.f32x2 %0, %1, %2, %3;" : "=l"(d) : "l"(a), "l"(b), "l"(c))

// ---------------------------------------------------------------------------
__global__ void detect_kernel(const int* __restrict__ ei) {
    if (threadIdx.x == 0) {
        int is64 = 1;
        #pragma unroll
        for (int i = 1; i < 64; i += 2)
            if (ei[i] != 0) is64 = 0;
        g_idx64 = is64;
    }
}

__global__ void prep_const_kernel(const float* __restrict__ ef,
                                  const float* __restrict__ tte,
                                  const float* __restrict__ W,
                                  const float* __restrict__ b) {
    int j = blockIdx.x * blockDim.x + threadIdx.x;
    if (j >= HID) return;
    float s0 = b[j], s1 = b[j];
    #pragma unroll 4
    for (int k = 0; k < 128; k++) {
        float w3 = W[(size_t)(256 + k) * HID + j];
        s0 += tte[k] * w3;
        s1 += tte[128 + k] * w3 + ef[k] * W[(size_t)k * HID + j];
    }
    g_c0[j] = s0;
    g_c1[j] = s1;
}

__global__ void prep_wc_kernel(const float* __restrict__ W) {
    int i = blockIdx.x * blockDim.x + threadIdx.x;   // 8192 float4
    float4 a = __ldg((const float4*)(W + 128 * HID) + i);
    float4 c = __ldg((const float4*)(W + 192 * HID) + i);
    a.x += c.x; a.y += c.y; a.z += c.z; a.w += c.w;
    ((float4*)g_Wc)[i] = a;
}

// ---------------------------------------------------------------------------
// Fused GEMM. 128x128 tile, BK=32, 256 threads, 8x8/thread, f32x2 FMA.
// k-loop FULLY unrolled (kq outer) so swizzle + LDS offsets constant-fold.
// ---------------------------------------------------------------------------
__global__ void __launch_bounds__(256, 2)
gemm_kernel(const float* __restrict__ nf, const float* __restrict__ pe,
            const float* __restrict__ W, float* __restrict__ out) {
    __shared__ float As[32 * 132];   // [k][m^swz]
    __shared__ float Bs[32 * 132];   // [k][n]

    const int tid = threadIdx.x;
    const int tx8 = (tid & 15) * 8;
    const int ty8 = (tid >> 4) * 8;
    const int bi = blockIdx.x;

    int row0, col0, nstages, is_node, uv = 0;
    if (bi < NB_ROW * 8) {
        is_node = 0;
        row0 = (bi >> 3) * 128;
        uv   = (bi & 7) >> 2;
        col0 = (bi & 3) * 128;
        nstages = 2;
    } else {
        is_node = 1;
        int jb = bi - NB_ROW * 8;
        row0 = (jb >> 2) * 128;
        col0 = (jb & 3) * 128;
        nstages = 6;
    }

    // Hoisted smem bases
    const char* bbase = (const char*)&Bs[tx8];

    ull acc[32];
    #pragma unroll
    for (int i = 0; i < 32; i++) acc[i] = 0ull;

    for (int s = 0; s < nstages; s++) {
        const float* Asrc; int L, kcol0;
        const float* Bsrc;
        if (!is_node) {
            Asrc = pe; L = 64; kcol0 = s * 32;
            Bsrc = W + (size_t)(128 + 64 * uv + s * 32) * HID + col0;
        } else {
            int kg = s * 32;
            if (kg < 128) { Asrc = nf; L = 128; kcol0 = kg;
                            Bsrc = W + (size_t)kg * HID + col0; }
            else          { Asrc = pe; L = 64;  kcol0 = kg - 128;
                            Bsrc = g_Wc + (size_t)(kg - 128) * HID + col0; }
        }

        // A tile (128 x 32) -> As[k][m^swz]
        #pragma unroll
        for (int i = 0; i < 4; i++) {
            int idx = i * 256 + tid;
            int m = idx >> 3, kq = idx & 7;
            int r = row0 + m;
            float4 v = (r < N_NODES)
                ? __ldg((const float4*)(Asrc + (size_t)r * L + kcol0) + kq)
                : make_float4(0.f, 0.f, 0.f, 0.f);
            int ms = m ^ (kq << 2);
            As[(kq * 4 + 0) * 132 + ms] = v.x;
            As[(kq * 4 + 1) * 132 + ms] = v.y;
            As[(kq * 4 + 2) * 132 + ms] = v.z;
            As[(kq * 4 + 3) * 132 + ms] = v.w;
        }
        // B tile (32 x 128)
        #pragma unroll
        for (int i = 0; i < 4; i++) {
            int idx = i * 256 + tid;
            int k = idx >> 5, n4 = idx & 31;
            float4 v = __ldg((const float4*)(Bsrc + (size_t)k * HID) + n4);
            *(float4*)&Bs[k * 132 + n4 * 4] = v;
        }
        __syncthreads();

        #pragma unroll
        for (int kq = 0; kq < 8; kq++) {
            const int x = kq << 2;                     // constant under unroll
            const float* ar0 = &As[ty8 ^ x];
            const float* ar1 = &As[(ty8 + 4) ^ x];
            #pragma unroll
            for (int kk = 0; kk < 4; kk++) {
                const int k = kq * 4 + kk;
                const float4 a0 = *(const float4*)(ar0 + k * 132);
                const float4 a1 = *(const float4*)(ar1 + k * 132);
                const ulonglong2* bp = (const ulonglong2*)(bbase + (size_t)k * 132 * 4);
                const ulonglong2 B0 = bp[0], B1 = bp[1];
                ull aa;
                aa = dup2(a0.x);
                FFMA2(acc[ 0], aa, B0.x, acc[ 0]); FFMA2(acc[ 1], aa, B0.y, acc[ 1]);
                FFMA2(acc[ 2], aa, B1.x, acc[ 2]); FFMA2(acc[ 3], aa, B1.y, acc[ 3]);
                aa = dup2(a0.y);
                FFMA2(acc[ 4], aa, B0.x, acc[ 4]); FFMA2(acc[ 5], aa, B0.y, acc[ 5]);
                FFMA2(acc[ 6], aa, B1.x, acc[ 6]); FFMA2(acc[ 7], aa, B1.y, acc[ 7]);
                aa = dup2(a0.z);
                FFMA2(acc[ 8], aa, B0.x, acc[ 8]); FFMA2(acc[ 9], aa, B0.y, acc[ 9]);
                FFMA2(acc[10], aa, B1.x, acc[10]); FFMA2(acc[11], aa, B1.y, acc[11]);
                aa = dup2(a0.w);
                FFMA2(acc[12], aa, B0.x, acc[12]); FFMA2(acc[13], aa, B0.y, acc[13]);
                FFMA2(acc[14], aa, B1.x, acc[14]); FFMA2(acc[15], aa, B1.y, acc[15]);
                aa = dup2(a1.x);
                FFMA2(acc[16], aa, B0.x, acc[16]); FFMA2(acc[17], aa, B0.y, acc[17]);
                FFMA2(acc[18], aa, B1.x, acc[18]); FFMA2(acc[19], aa, B1.y, acc[19]);
                aa = dup2(a1.y);
                FFMA2(acc[20], aa, B0.x, acc[20]); FFMA2(acc[21], aa, B0.y, acc[21]);
                FFMA2(acc[22], aa, B1.x, acc[22]); FFMA2(acc[23], aa, B1.y, acc[23]);
                aa = dup2(a1.z);
                FFMA2(acc[24], aa, B0.x, acc[24]); FFMA2(acc[25], aa, B0.y, acc[25]);
                FFMA2(acc[26], aa, B1.x, acc[26]); FFMA2(acc[27], aa, B1.y, acc[27]);
                aa = dup2(a1.w);
                FFMA2(acc[28], aa, B0.x, acc[28]); FFMA2(acc[29], aa, B0.y, acc[29]);
                FFMA2(acc[30], aa, B1.x, acc[30]); FFMA2(acc[31], aa, B1.y, acc[31]);
            }
        }
        __syncthreads();
    }

    if (!is_node) {
        __half* Out = uv ? g_Vh : g_Uh;
        #pragma unroll
        for (int m = 0; m < 8; m++) {
            int r = row0 + ty8 + m;
            if (r < N_NODES) {
                float f0, f1, f2, f3, f4, f5, f6, f7;
                unpack2(acc[m * 4 + 0], f0, f1);
                unpack2(acc[m * 4 + 1], f2, f3);
                unpack2(acc[m * 4 + 2], f4, f5);
                unpack2(acc[m * 4 + 3], f6, f7);
                uint4 pk;
                __half2* ph = (__half2*)&pk;
                ph[0] = __floats2half2_rn(f0, f1);
                ph[1] = __floats2half2_rn(f2, f3);
                ph[2] = __floats2half2_rn(f4, f5);
                ph[3] = __floats2half2_rn(f6, f7);
                *(uint4*)(Out + (size_t)r * HID + col0 + tx8) = pk;
            }
        }
    } else {
        const float4 cA = *(const float4*)&g_c0[col0 + tx8];
        const float4 cB = *(const float4*)&g_c0[col0 + tx8 + 4];
        #pragma unroll
        for (int m = 0; m < 8; m++) {
            int r = row0 + ty8 + m;
            if (r < N_NODES) {
                float4 o0, o1;
                unpack2(acc[m * 4 + 0], o0.x, o0.y);
                unpack2(acc[m * 4 + 1], o0.z, o0.w);
                unpack2(acc[m * 4 + 2], o1.x, o1.y);
                unpack2(acc[m * 4 + 3], o1.z, o1.w);
                o0.x += cA.x; o0.y += cA.y; o0.z += cA.z; o0.w += cA.w;
                o1.x += cB.x; o1.y += cB.y; o1.z += cB.z; o1.w += cB.w;
                float* dst = out + (size_t)r * HID + col0 + tx8;
                __stcs((float4*)dst, o0);
                __stcs((float4*)(dst + 4), o1);
            }
        }
    }
}

// ---------------------------------------------------------------------------
// Edge rows: out[N+e] = Uh[src] + Vh[dst] + c1. Two edges per thread for 2x
// memory-level parallelism (4 independent gathers in flight).
// ---------------------------------------------------------------------------
__global__ void __launch_bounds__(256)
edge_kernel(const int* __restrict__ ei, float* __restrict__ out) {
    long long t = (long long)blockIdx.x * 256 + threadIdx.x;
    int p = (int)(t >> 6);          // edge-pair index
    int c = (int)(t & 63);          // uint4 column within row
    int e0 = p * 2, e1 = e0 + 1;
    if (e1 >= N_EDGES + 1) return;  // N_EDGES even; p < N_EDGES/2 always

    int s0, d0, s1, d1;
    if (g_idx64) {
        s0 = ei[2 * (size_t)e0];
        d0 = ei[2 * ((size_t)N_EDGES + e0)];
        s1 = ei[2 * (size_t)e1];
        d1 = ei[2 * ((size_t)N_EDGES + e1)];
    } else {
        s0 = ei[e0];  d0 = ei[N_EDGES + e0];
        s1 = ei[e1];  d1 = ei[N_EDGES + e1];
    }

    // Issue all four gathers before any conversion (max MLP)
    uint4 pu0 = __ldg((const uint4*)(g_Uh + (size_t)s0 * HID) + c);
    uint4 pv0 = __ldg((const uint4*)(g_Vh + (size_t)d0 * HID) + c);
    uint4 pu1 = __ldg((const uint4*)(g_Uh + (size_t)s1 * HID) + c);
    uint4 pv1 = __ldg((const uint4*)(g_Vh + (size_t)d1 * HID) + c);
    float4 c1a = __ldg((const float4*)g_c1 + c * 2);
    float4 c1b = __ldg((const float4*)g_c1 + c * 2 + 1);

    const __half2* hu0 = (const __half2*)&pu0;
    const __half2* hv0 = (const __half2*)&pv0;
    const __half2* hu1 = (const __half2*)&pu1;
    const __half2* hv1 = (const __half2*)&pv1;

    float4 o0, o1;
    {
        float2 a0 = __half22float2(hu0[0]), a1 = __half22float2(hu0[1]);
        float2 a2 = __half22float2(hu0[2]), a3 = __half22float2(hu0[3]);
        float2 b0 = __half22float2(hv0[0]), b1 = __half22float2(hv0[1]);
        float2 b2 = __half22float2(hv0[2]), b3 = __half22float2(hv0[3]);
        o0.x = a0.x + b0.x + c1a.x;  o0.y = a0.y + b0.y + c1a.y;
        o0.z = a1.x + b1.x + c1a.z;  o0.w = a1.y + b1.y + c1a.w;
        o1.x = a2.x + b2.x + c1b.x;  o1.y = a2.y + b2.y + c1b.y;
        o1.z = a3.x + b3.x + c1b.z;  o1.w = a3.y + b3.y + c1b.w;
    }
    float* dp0 = out + (size_t)(N_NODES + e0) * HID + c * 8;
    __stcs((float4*)dp0, o0);
    __stcs((float4*)(dp0 + 4), o1);

    {
        float2 a0 = __half22float2(hu1[0]), a1 = __half22float2(hu1[1]);
        float2 a2 = __half22float2(hu1[2]), a3 = __half22float2(hu1[3]);
        float2 b0 = __half22float2(hv1[0]), b1 = __half22float2(hv1[1]);
        float2 b2 = __half22float2(hv1[2]), b3 = __half22float2(hv1[3]);
        o0.x = a0.x + b0.x + c1a.x;  o0.y = a0.y + b0.y + c1a.y;
        o0.z = a1.x + b1.x + c1a.z;  o0.w = a1.y + b1.y + c1a.w;
        o1.x = a2.x + b2.x + c1b.x;  o1.y = a2.y + b2.y + c1b.y;
        o1.z = a3.x + b3.x + c1b.z;  o1.w = a3.y + b3.y + c1b.w;
    }
    float* dp1 = out + (size_t)(N_NODES + e1) * HID + c * 8;
    __stcs((float4*)dp1, o0);
    __stcs((float4*)(dp1 + 4), o1);
}

// ---------------------------------------------------------------------------
extern "C" void kernel_launch(void* const* d_in, const int* in_sizes, int n_in,
                              void* d_out, int out_size) {
    const void* ptr[7] = {d_in[0], d_in[1], d_in[2], d_in[3], d_in[4], d_in[5], d_in[6]};
    const int want[7] = {6400000, 3200000, 128, 256, 196608, 512, 1600000};
    const void* mapped[7];
    for (int w = 0; w < 7; w++) {
        mapped[w] = ptr[w < n_in ? w : 0];
        for (int i = 0; i < n_in && i < 7; i++)
            if (in_sizes[i] == want[w]) { mapped[w] = ptr[i]; break; }
    }
    const float* nf  = (const float*)mapped[0];
    const float* pe  = (const float*)mapped[1];
    const float* ef  = (const float*)mapped[2];
    const float* tte = (const float*)mapped[3];
    const float* W   = (const float*)mapped[4];
    const float* b   = (const float*)mapped[5];
    const int*   ei  = (const int*)mapped[6];
    float* out = (float*)d_out;

    detect_kernel<<<1, 32>>>(ei);
    prep_const_kernel<<<2, 256>>>(ef, tte, W, b);
    prep_wc_kernel<<<32, 256>>>(W);
    gemm_kernel<<<NB_ROW * 12, 256>>>(nf, pe, W, out);
    edge_kernel<<<(N_EDGES / 2 * 64) / 256, 256>>>(ei, out);
}